// round 16
// baseline (speedup 1.0000x reference)
#include <cuda_runtime.h>
#include <cuda_fp16.h>
#include <cstdint>
#include <cstddef>
#include <math.h>

#define H2d 4
#define Bsz 16
#define Cc 64
#define Nn 64
#define Dd 512
#define Ll (Nn*Cc)            // 4096
#define M3 (3*Dd)             // 1536
#define LDm 68                // padded smem pitch (floats)
#define HP 72                 // padded smem pitch (halves) -> 144B
#define SCALE_ATT 0.125f
#define SPD_EPSF 1e-5f

#define MROWS (Bsz*Ll)        // 65536
#define KK 512
#define BK 64
#define NCH 8
#define BMg 128
#define BNg 256
#define APITCH 72
#define STGB_H ((BMg+BNg)*APITCH)       // halves per stage = 27648
#define GSM (3*STGB_H*2)                // 165888 bytes

// ---------------- scratch ----------------
__device__ __half g_qkv[(size_t)Bsz * Ll * M3];           // fp16 QKV
__device__ __half g_abuf[(size_t)MROWS * KK];             // fp16 x (stays intact)
__device__ __half g_obuf[(size_t)MROWS * KK];             // fp16 attention outputs
__device__ __half g_wbuf[(size_t)M3 * KK];                // fp16 weights

// =================================================================
// PTX helpers
// =================================================================
__device__ __forceinline__ uint32_t smem_u32(const void* p) {
    uint32_t a;
    asm("{ .reg .u64 t; cvta.to.shared.u64 t, %1; cvt.u32.u64 %0, t; }" : "=r"(a) : "l"(p));
    return a;
}
#define CP_ASYNC16(dst, src) \
    asm volatile("cp.async.cg.shared.global [%0], [%1], 16;" :: "r"(dst), "l"(src))
#define CP_COMMIT() asm volatile("cp.async.commit_group;" ::: "memory")
#define CP_WAIT1()  asm volatile("cp.async.wait_group 1;" ::: "memory")

__device__ __forceinline__ void ldsm_x4(uint32_t& r0, uint32_t& r1, uint32_t& r2,
                                        uint32_t& r3, uint32_t addr) {
    asm volatile("ldmatrix.sync.aligned.m8n8.x4.shared.b16 {%0,%1,%2,%3}, [%4];"
                 : "=r"(r0), "=r"(r1), "=r"(r2), "=r"(r3) : "r"(addr));
}
__device__ __forceinline__ void ldsm_x4_t(uint32_t& r0, uint32_t& r1, uint32_t& r2,
                                          uint32_t& r3, uint32_t addr) {
    asm volatile("ldmatrix.sync.aligned.m8n8.x4.trans.shared.b16 {%0,%1,%2,%3}, [%4];"
                 : "=r"(r0), "=r"(r1), "=r"(r2), "=r"(r3) : "r"(addr));
}
__device__ __forceinline__ void mma16816(float c[4], uint32_t a0, uint32_t a1,
                                         uint32_t a2, uint32_t a3,
                                         uint32_t b0, uint32_t b1) {
    asm volatile(
        "mma.sync.aligned.m16n8k16.row.col.f32.f16.f16.f32 "
        "{%0,%1,%2,%3}, {%4,%5,%6,%7}, {%8,%9}, {%0,%1,%2,%3};"
        : "+f"(c[0]), "+f"(c[1]), "+f"(c[2]), "+f"(c[3])
        : "r"(a0), "r"(a1), "r"(a2), "r"(a3), "r"(b0), "r"(b1));
}

// =================================================================
// fp32 -> fp16 cast (global)
// =================================================================
__global__ void conv_cast(const float* __restrict__ src, __half* __restrict__ dst,
                          size_t total)
{
    size_t i = (size_t)blockIdx.x * blockDim.x + threadIdx.x;
    size_t e = i * 4;
    if (e >= total) return;
    float4 v = *(const float4*)(src + e);
    *(__half2*)(dst + e)     = __floats2half2_rn(v.x, v.y);
    *(__half2*)(dst + e + 2) = __floats2half2_rn(v.z, v.w);
}

// =================================================================
// mma.sync fp16 GEMM: 128x256 CTA tile, warp tile 64x64 (2x4 warps),
// BK=64, 3-stage cp.async. Doubles FLOP/smem-byte vs 128x128.
// =================================================================
template<bool HALF_OUT>
__global__ __launch_bounds__(256, 1) void gemm_mma(
    const __half* __restrict__ A, const __half* __restrict__ W,
    const float* __restrict__ bias, void* __restrict__ Cv, int Nout)
{
    extern __shared__ __half smg[];
    const int tid = threadIdx.x;
    const int wid = tid >> 5, lane = tid & 31;
    const int g = lane >> 2, tig = lane & 3;
    const int warp_m = wid >> 2, warp_n = wid & 3;     // 2 x 4
    const int bc = blockIdx.x, br = blockIdx.y;

    const __half* gAb = A + (size_t)(br * BMg) * KK;
    const __half* gBb = W + (size_t)(bc * BNg) * KK;

    const uint32_t smb = smem_u32(smg);

    auto load_chunk = [&](int kc, int s) {
        const uint32_t smA = smb + (uint32_t)(s * STGB_H) * 2;
        const uint32_t smB = smA + (uint32_t)(BMg * APITCH) * 2;
        const __half* gA = gAb + kc * BK;
        const __half* gB = gBb + kc * BK;
#pragma unroll
        for (int i = 0; i < 4; i++) {       // A: 128 rows x 8 x 16B
            int idx = i * 256 + tid;
            int r = idx >> 3, c16 = idx & 7;
            CP_ASYNC16(smA + r * (APITCH * 2) + c16 * 16, gA + (size_t)r * KK + c16 * 8);
        }
#pragma unroll
        for (int i = 0; i < 8; i++) {       // B: 256 rows x 8 x 16B
            int idx = i * 256 + tid;
            int r = idx >> 3, c16 = idx & 7;
            CP_ASYNC16(smB + r * (APITCH * 2) + c16 * 16, gB + (size_t)r * KK + c16 * 8);
        }
    };

    float acc[4][8][4];
#pragma unroll
    for (int mt = 0; mt < 4; mt++)
#pragma unroll
        for (int nt = 0; nt < 8; nt++)
#pragma unroll
            for (int q = 0; q < 4; q++) acc[mt][nt][q] = 0.f;

    const int a_row = warp_m * 64 + (lane & 15);
    const int a_kof = (lane >> 4) * 8;
    const int b_col = warp_n * 64 + (lane & 7) + ((lane >> 4) << 3);
    const int b_kof = ((lane >> 3) & 1) * 8;

    load_chunk(0, 0); CP_COMMIT();
    load_chunk(1, 1); CP_COMMIT();

    for (int kc = 0; kc < NCH; kc++) {
        CP_WAIT1();
        __syncthreads();
        if (kc + 2 < NCH) load_chunk(kc + 2, (kc + 2) % 3);
        CP_COMMIT();

        const int s = kc % 3;
        const uint32_t smA = smb + (uint32_t)(s * STGB_H) * 2;
        const uint32_t smB = smA + (uint32_t)(BMg * APITCH) * 2;

#pragma unroll
        for (int ks = 0; ks < 4; ks++) {
            const int kb = ks * 16;
            uint32_t af[4][4], bf[4][4];
#pragma unroll
            for (int mt = 0; mt < 4; mt++) {
                uint32_t addr = smA + (uint32_t)(((a_row + mt * 16) * APITCH) + kb + a_kof) * 2;
                ldsm_x4(af[mt][0], af[mt][1], af[mt][2], af[mt][3], addr);
            }
#pragma unroll
            for (int ntp = 0; ntp < 4; ntp++) {
                uint32_t addr = smB + (uint32_t)(((b_col + ntp * 16) * APITCH) + kb + b_kof) * 2;
                ldsm_x4(bf[ntp][0], bf[ntp][1], bf[ntp][2], bf[ntp][3], addr);
            }
#pragma unroll
            for (int mt = 0; mt < 4; mt++)
#pragma unroll
                for (int ntp = 0; ntp < 4; ntp++) {
                    mma16816(acc[mt][2 * ntp],     af[mt][0], af[mt][1], af[mt][2], af[mt][3],
                             bf[ntp][0], bf[ntp][1]);
                    mma16816(acc[mt][2 * ntp + 1], af[mt][0], af[mt][1], af[mt][2], af[mt][3],
                             bf[ntp][2], bf[ntp][3]);
                }
        }
    }

#pragma unroll
    for (int mt = 0; mt < 4; mt++) {
        int row0 = br * BMg + warp_m * 64 + mt * 16 + g;
#pragma unroll
        for (int nt = 0; nt < 8; nt++) {
            int col = bc * BNg + warp_n * 64 + nt * 8 + 2 * tig;
            float b0 = bias[col], b1 = bias[col + 1];
            if (HALF_OUT) {
                __half* C = (__half*)Cv;
                *(__half2*)(C + (size_t)row0 * Nout + col) =
                    __floats2half2_rn(acc[mt][nt][0] + b0, acc[mt][nt][1] + b1);
                *(__half2*)(C + (size_t)(row0 + 8) * Nout + col) =
                    __floats2half2_rn(acc[mt][nt][2] + b0, acc[mt][nt][3] + b1);
            } else {
                float* C = (float*)Cv;
                *(float2*)(C + (size_t)row0 * Nout + col) =
                    make_float2(acc[mt][nt][0] + b0, acc[mt][nt][1] + b1);
                *(float2*)(C + (size_t)(row0 + 8) * Nout + col) =
                    make_float2(acc[mt][nt][2] + b0, acc[mt][nt][3] + b1);
            }
        }
    }
}

// =================================================================
// Scalar 64x64 matmul helpers (fp32; final NS iter only)
// =================================================================
__device__ __forceinline__ void mm64s_acc(float acc[4][4],
                                          const float* __restrict__ Am,
                                          const float* __restrict__ Bm,
                                          int tx, int ty)
{
#pragma unroll 8
    for (int k = 0; k < 64; k++) {
        float4 bv = *(const float4*)(Bm + k * LDm + 4 * tx);
        float a0 = Am[(4 * ty + 0) * LDm + k];
        float a1 = Am[(4 * ty + 1) * LDm + k];
        float a2 = Am[(4 * ty + 2) * LDm + k];
        float a3 = Am[(4 * ty + 3) * LDm + k];
        acc[0][0] += a0 * bv.x; acc[0][1] += a0 * bv.y; acc[0][2] += a0 * bv.z; acc[0][3] += a0 * bv.w;
        acc[1][0] += a1 * bv.x; acc[1][1] += a1 * bv.y; acc[1][2] += a1 * bv.z; acc[1][3] += a1 * bv.w;
        acc[2][0] += a2 * bv.x; acc[2][1] += a2 * bv.y; acc[2][2] += a2 * bv.z; acc[2][3] += a2 * bv.w;
        acc[3][0] += a3 * bv.x; acc[3][1] += a3 * bv.y; acc[3][2] += a3 * bv.z; acc[3][3] += a3 * bv.w;
    }
}
__device__ __forceinline__ void mm64(float* __restrict__ dst,
                                     const float* __restrict__ Am,
                                     const float* __restrict__ Bm,
                                     int tx, int ty, float dscale, float diagadd)
{
    float acc[4][4] = {};
    mm64s_acc(acc, Am, Bm, tx, ty);
#pragma unroll
    for (int i = 0; i < 4; i++)
#pragma unroll
        for (int j = 0; j < 4; j++) {
            int r = 4 * ty + i, c = 4 * tx + j;
            dst[r * LDm + c] = acc[i][j] * dscale + ((r == c) ? diagadd : 0.f);
        }
    __syncthreads();
}

// =================================================================
// mma 64x64 matmul on smem fp16 operands, fp32 smem output.
// =================================================================
__device__ __forceinline__ void mm64h_store(float* dst, const float acc[4][4],
                                            int m0, int n0, int g, int tig,
                                            float dscale, float diagadd)
{
#pragma unroll
    for (int nt = 0; nt < 4; nt++) {
        int r = m0 + g, c = n0 + nt * 8 + 2 * tig;
        dst[r * LDm + c]           = acc[nt][0] * dscale + ((r == c)         ? diagadd : 0.f);
        dst[r * LDm + c + 1]       = acc[nt][1] * dscale + ((r == c + 1)     ? diagadd : 0.f);
        dst[(r + 8) * LDm + c]     = acc[nt][2] * dscale + ((r + 8 == c)     ? diagadd : 0.f);
        dst[(r + 8) * LDm + c + 1] = acc[nt][3] * dscale + ((r + 8 == c + 1) ? diagadd : 0.f);
    }
}

template<bool TRANS>
__device__ __forceinline__ void mm64h(float* dst, const __half* Ah, const __half* Bh,
                                      float dscale, float diagadd, int tid)
{
    const int wid = tid >> 5, lane = tid & 31;
    const int g = lane >> 2, tig = lane & 3;
    const int m0 = (wid >> 1) * 16, n0 = (wid & 1) * 32;
    const uint32_t ab = smem_u32(Ah), bb = smem_u32(Bh);
    const int a_off = (m0 + (lane & 15)) * HP + (lane >> 4) * 8;
    const int b_off = (n0 + (lane & 7) + ((lane >> 4) << 3)) * HP + ((lane >> 3) & 1) * 8;
    const int v_off = (lane & 15) * HP + n0 + ((lane >> 4) << 3);

    float acc[4][4];
#pragma unroll
    for (int i = 0; i < 4; i++)
#pragma unroll
        for (int j = 0; j < 4; j++) acc[i][j] = 0.f;

#pragma unroll
    for (int ks = 0; ks < 4; ks++) {
        uint32_t a[4], b0[4], b1[4];
        ldsm_x4(a[0], a[1], a[2], a[3], ab + (uint32_t)(a_off + ks * 16) * 2);
        if (TRANS) {
            ldsm_x4_t(b0[0], b0[1], b0[2], b0[3], bb + (uint32_t)(v_off + ks * 16 * HP) * 2);
            ldsm_x4_t(b1[0], b1[1], b1[2], b1[3], bb + (uint32_t)(v_off + ks * 16 * HP + 16) * 2);
        } else {
            ldsm_x4(b0[0], b0[1], b0[2], b0[3], bb + (uint32_t)(b_off + ks * 16) * 2);
            ldsm_x4(b1[0], b1[1], b1[2], b1[3], bb + (uint32_t)(b_off + 16 * HP + ks * 16) * 2);
        }
        mma16816(acc[0], a[0], a[1], a[2], a[3], b0[0], b0[1]);
        mma16816(acc[1], a[0], a[1], a[2], a[3], b0[2], b0[3]);
        mma16816(acc[2], a[0], a[1], a[2], a[3], b1[0], b1[1]);
        mma16816(acc[3], a[0], a[1], a[2], a[3], b1[2], b1[3]);
    }
    mm64h_store(dst, acc, m0, n0, g, tig, dscale, diagadd);
    __syncthreads();
}

// cast 64x64 fp32 (pitch LDm) -> fp16 (pitch HP); trailing sync
__device__ __forceinline__ void cast64(__half* dst, const float* src, int tid)
{
#pragma unroll
    for (int it = 0; it < 4; it++) {
        int idx = it * 256 + tid;
        int r = idx >> 4, c4 = (idx & 15) * 4;
        float4 v = *(const float4*)(src + r * LDm + c4);
        *(__half2*)(dst + r * HP + c4)     = __floats2half2_rn(v.x, v.y);
        *(__half2*)(dst + r * HP + c4 + 2) = __floats2half2_rn(v.z, v.w);
    }
    __syncthreads();
}

// =================================================================
// attn64_mma (validated R14/R15)
// =================================================================
__device__ __forceinline__ void attn64_mma(
    const __half* Qh, const __half* Kh, const __half* Vh, __half* Ph,
    float* Sf, const float* bias, float hs,
    size_t rowbase, int rstride, int colbase, int tid)
{
    const int wid = tid >> 5, lane = tid & 31;
    const int g = lane >> 2, tig = lane & 3;
    const int m0 = (wid >> 1) * 16, n0 = (wid & 1) * 32;

    const uint32_t qb = smem_u32(Qh);
    const uint32_t kb = smem_u32(Kh);
    const uint32_t vb = smem_u32(Vh);
    const uint32_t pb = smem_u32(Ph);

    const int a_off = (m0 + (lane & 15)) * HP + (lane >> 4) * 8;
    const int b_off = (n0 + (lane & 7) + ((lane >> 4) << 3)) * HP + ((lane >> 3) & 1) * 8;
    const int v_off = (lane & 15) * HP + n0 + ((lane >> 4) << 3);

    float acc[4][4];
#pragma unroll
    for (int i = 0; i < 4; i++)
#pragma unroll
        for (int j = 0; j < 4; j++) acc[i][j] = 0.f;

#pragma unroll
    for (int ks = 0; ks < 4; ks++) {
        uint32_t a[4], b0[4], b1[4];
        ldsm_x4(a[0], a[1], a[2], a[3], qb + (uint32_t)(a_off + ks * 16) * 2);
        ldsm_x4(b0[0], b0[1], b0[2], b0[3], kb + (uint32_t)(b_off + ks * 16) * 2);
        ldsm_x4(b1[0], b1[1], b1[2], b1[3], kb + (uint32_t)(b_off + 16 * HP + ks * 16) * 2);
        mma16816(acc[0], a[0], a[1], a[2], a[3], b0[0], b0[1]);
        mma16816(acc[1], a[0], a[1], a[2], a[3], b0[2], b0[3]);
        mma16816(acc[2], a[0], a[1], a[2], a[3], b1[0], b1[1]);
        mma16816(acc[3], a[0], a[1], a[2], a[3], b1[2], b1[3]);
    }
#pragma unroll
    for (int nt = 0; nt < 4; nt++) {
        int r = m0 + g, c = n0 + nt * 8 + 2 * tig;
        float s0 = acc[nt][0] * SCALE_ATT, s1 = acc[nt][1] * SCALE_ATT;
        float s2 = acc[nt][2] * SCALE_ATT, s3 = acc[nt][3] * SCALE_ATT;
        if (bias) {
            s0 += hs * bias[r * LDm + c];       s1 += hs * bias[r * LDm + c + 1];
            s2 += hs * bias[(r + 8) * LDm + c]; s3 += hs * bias[(r + 8) * LDm + c + 1];
        }
        Sf[r * LDm + c] = s0;       Sf[r * LDm + c + 1] = s1;
        Sf[(r + 8) * LDm + c] = s2; Sf[(r + 8) * LDm + c + 1] = s3;
    }
    __syncthreads();

    {
        int row = tid >> 2, seg = tid & 3;
        const float* src = Sf + row * LDm + seg * 16;
        float vv[16];
        float4 t0 = *(const float4*)(src);
        float4 t1 = *(const float4*)(src + 4);
        float4 t2 = *(const float4*)(src + 8);
        float4 t3 = *(const float4*)(src + 12);
        vv[0] = t0.x; vv[1] = t0.y; vv[2] = t0.z; vv[3] = t0.w;
        vv[4] = t1.x; vv[5] = t1.y; vv[6] = t1.z; vv[7] = t1.w;
        vv[8] = t2.x; vv[9] = t2.y; vv[10] = t2.z; vv[11] = t2.w;
        vv[12] = t3.x; vv[13] = t3.y; vv[14] = t3.z; vv[15] = t3.w;
        float m = vv[0];
#pragma unroll
        for (int j = 1; j < 16; j++) m = fmaxf(m, vv[j]);
        m = fmaxf(m, __shfl_xor_sync(0xffffffffu, m, 1, 4));
        m = fmaxf(m, __shfl_xor_sync(0xffffffffu, m, 2, 4));
        float s = 0.f;
#pragma unroll
        for (int j = 0; j < 16; j++) { vv[j] = __expf(vv[j] - m); s += vv[j]; }
        s += __shfl_xor_sync(0xffffffffu, s, 1, 4);
        s += __shfl_xor_sync(0xffffffffu, s, 2, 4);
        float inv = 1.f / s;
        __half* d = Ph + row * HP + seg * 16;
#pragma unroll
        for (int j = 0; j < 8; j++)
            *(__half2*)(d + 2 * j) = __floats2half2_rn(vv[2 * j] * inv, vv[2 * j + 1] * inv);
    }
    __syncthreads();

    float o[4][4];
#pragma unroll
    for (int i = 0; i < 4; i++)
#pragma unroll
        for (int j = 0; j < 4; j++) o[i][j] = 0.f;

#pragma unroll
    for (int ks = 0; ks < 4; ks++) {
        uint32_t a[4], b0[4], b1[4];
        ldsm_x4(a[0], a[1], a[2], a[3], pb + (uint32_t)(a_off + ks * 16) * 2);
        ldsm_x4_t(b0[0], b0[1], b0[2], b0[3], vb + (uint32_t)(v_off + ks * 16 * HP) * 2);
        ldsm_x4_t(b1[0], b1[1], b1[2], b1[3], vb + (uint32_t)(v_off + ks * 16 * HP + 16) * 2);
        mma16816(o[0], a[0], a[1], a[2], a[3], b0[0], b0[1]);
        mma16816(o[1], a[0], a[1], a[2], a[3], b0[2], b0[3]);
        mma16816(o[2], a[0], a[1], a[2], a[3], b1[0], b1[1]);
        mma16816(o[3], a[0], a[1], a[2], a[3], b1[2], b1[3]);
    }
#pragma unroll
    for (int nt = 0; nt < 4; nt++) {
        int r = m0 + g, c = colbase + n0 + nt * 8 + 2 * tig;
        __half* d0 = g_obuf + (rowbase + (size_t)r * rstride) * KK + c;
        __half* d1 = g_obuf + (rowbase + (size_t)(r + 8) * rstride) * KK + c;
        *(__half2*)d0 = __floats2half2_rn(o[nt][0], o[nt][1]);
        *(__half2*)d1 = __floats2half2_rn(o[nt][2], o[nt][3]);
    }
}

// =================================================================
// Temporal attention (validated R14)
// =================================================================
__global__ __launch_bounds__(256, 2) void temporal_attn()
{
    extern __shared__ char smT[];
    __half* Qh = (__half*)smT;
    __half* Kh = Qh + 64 * HP;
    __half* Vh = Kh + 64 * HP;
    float*  Sf = (float*)(smT + 3 * 64 * HP * 2);
    const int tid = threadIdx.x;
    const int h = blockIdx.x & 3;
    const int c = (blockIdx.x >> 2) & 63;
    const int b = blockIdx.x >> 8;

    const __half* qk = g_qkv + (size_t)b * Ll * M3 + h * 64;
#pragma unroll
    for (int it = 0; it < 8; it++) {
        int idx = it * 256 + tid;
        int nn = idx >> 5, e2 = (idx & 31) * 2;
        const __half* p = qk + (size_t)(nn * Cc + c) * M3 + e2;
        *(__half2*)(Qh + nn * HP + e2) = *(const __half2*)(p);
        *(__half2*)(Kh + nn * HP + e2) = *(const __half2*)(p + Dd);
        *(__half2*)(Vh + nn * HP + e2) = *(const __half2*)(p + 2 * Dd);
    }
    __syncthreads();

    attn64_mma(Qh, Kh, Vh, Qh, Sf, nullptr, 0.f,
               (size_t)b * Ll + c, 64, h * 64, tid);
}

// =================================================================
// Spatial (validated R15): mma S-build, fp16-mma NS(3)+fp32 final,
// fp16-mma polynomial, mma attention.
// =================================================================
__global__ __launch_bounds__(256, 2) void spatial_riemann(
    const float* __restrict__ head_scales)
{
    extern __shared__ char smS[];
    float* F0 = (float*)smS;
    float* F1 = (float*)(smS + 17408);
    float* F2 = (float*)(smS + 34816);
    __half* H0 = (__half*)(smS + 52224);
    __half* H1 = (__half*)(smS + 61440);
    __half* H2 = (__half*)(smS + 70656);
    float* red = (float*)(smS + 79872);
    __shared__ float s_alpha;

    const int tid = threadIdx.x, tx = tid & 15, ty = tid >> 4;
    const int lane = tid & 31, wid = tid >> 5;
    const int g = lane >> 2, tig = lane & 3;
    const int m0 = (wid >> 1) * 16, n0 = (wid & 1) * 32;
    const int n = blockIdx.x & 63, b = blockIdx.x >> 6;

    // ---- A = X X^T / D + (1+eps) I  via mma over fp16 x (g_abuf) ----
    {
        const size_t xrow0 = (size_t)b * Ll + (size_t)n * Cc;
        float sacc[4][4];
#pragma unroll
        for (int i = 0; i < 4; i++)
#pragma unroll
            for (int j = 0; j < 4; j++) sacc[i][j] = 0.f;

        const uint32_t xb = smem_u32(H0);
        const int a_off = (m0 + (lane & 15)) * HP + (lane >> 4) * 8;
        const int b_off = (n0 + (lane & 7) + ((lane >> 4) << 3)) * HP + ((lane >> 3) & 1) * 8;

        for (int kc = 0; kc < 8; kc++) {
#pragma unroll
            for (int it = 0; it < 8; it++) {
                int idx = it * 256 + tid;
                int r = idx >> 5, e2 = (idx & 31) * 2;
                *(__half2*)(H0 + r * HP + e2) =
                    *(const __half2*)(g_abuf + (xrow0 + r) * KK + kc * 64 + e2);
            }
            __syncthreads();
#pragma unroll
            for (int ks = 0; ks < 4; ks++) {
                uint32_t a[4], b0[4], b1[4];
                ldsm_x4(a[0], a[1], a[2], a[3], xb + (uint32_t)(a_off + ks * 16) * 2);
                ldsm_x4(b0[0], b0[1], b0[2], b0[3], xb + (uint32_t)(b_off + ks * 16) * 2);
                ldsm_x4(b1[0], b1[1], b1[2], b1[3], xb + (uint32_t)(b_off + 16 * HP + ks * 16) * 2);
                mma16816(sacc[0], a[0], a[1], a[2], a[3], b0[0], b0[1]);
                mma16816(sacc[1], a[0], a[1], a[2], a[3], b0[2], b0[3]);
                mma16816(sacc[2], a[0], a[1], a[2], a[3], b1[0], b1[1]);
                mma16816(sacc[3], a[0], a[1], a[2], a[3], b1[2], b1[3]);
            }
            __syncthreads();
        }
        mm64h_store(F0, sacc, m0, n0, g, tig, 1.f / (float)Dd, 1.f + SPD_EPSF);
        __syncthreads();
    }

    // ---- Gershgorin -> alpha ----
    {
        int r = tid >> 2, seg = tid & 3;
        float s = 0.f;
#pragma unroll
        for (int j = 0; j < 16; j++) s += fabsf(F0[r * LDm + seg * 16 + j]);
        red[tid] = s;
    }
    __syncthreads();
    if (tid == 0) {
        float rmax = 0.f;
        for (int r = 0; r < 64; r++)
            rmax = fmaxf(rmax, red[4 * r] + red[4 * r + 1] + red[4 * r + 2] + red[4 * r + 3]);
        s_alpha = 2.f / (1.f + rmax);
    }
    __syncthreads();
    const float alpha = s_alpha;

    cast64(H1, F0, tid);
#pragma unroll
    for (int it = 0; it < 16; it++) {
        int idx = it * 256 + tid;
        int r = idx >> 6, c = idx & 63;
        H0[r * HP + c] = __float2half((r == c) ? alpha : 0.f);
    }
    __syncthreads();

    // ---- NS iterations 1-3 in fp16 mma ----
    for (int it = 0; it < 3; it++) {
        mm64h<false>(F1, H1, H0, 1.f, 0.f, tid);
        cast64(H2, F1, tid);
        mm64h<true>(F1, H0, H2, 1.f, 0.f, tid);
#pragma unroll
        for (int i2 = 0; i2 < 16; i2++) {
            int idx = i2 * 256 + tid;
            int r = idx >> 6, c = idx & 63;
            float y = __half2float(H0[r * HP + c]);
            H0[r * HP + c] = __float2half(2.f * y - F1[r * LDm + c]);
        }
        __syncthreads();
    }

    // ---- final NS iteration fp32 ----
#pragma unroll
    for (int it = 0; it < 16; it++) {
        int idx = it * 256 + tid;
        int r = idx >> 6, c = idx & 63;
        F1[r * LDm + c] = __half2float(H0[r * HP + c]);
    }
    __syncthreads();
    mm64(F2, F0, F1, tx, ty, 1.f, 0.f);
    mm64(F0, F1, F2, tx, ty, 1.f, 0.f);
#pragma unroll
    for (int it = 0; it < 16; it++) {
        int idx = it * 256 + tid;
        int r = idx >> 6, c = idx & 63;
        float y = 2.f * F1[r * LDm + c] - F0[r * LDm + c];
        H0[r * HP + c] = __float2half(((r == c) ? 1.f : 0.f) - 2.f * y);
    }
    __syncthreads();

    // ---- polynomial chain ----
    mm64h<false>(F0, H0, H0, 1.f, 0.f, tid);   // W
    cast64(H1, F0, tid);
    mm64h<false>(F1, H1, H1, 1.f, 0.f, tid);   // W2
    cast64(H2, F1, tid);
    mm64h<false>(F2, H2, H1, 1.f, 0.f, tid);   // W3
    cast64(H1, F2, tid);

#pragma unroll
    for (int it = 0; it < 16; it++) {
        int idx = it * 256 + tid;
        int r = idx >> 6, c = idx & 63;
        F2[r * LDm + c] = ((r == c) ? (1.f / 7.f) : 0.f)
                        + F0[r * LDm + c] * (1.f / 9.f)
                        + F1[r * LDm + c] * (1.f / 11.f);
    }
    __syncthreads();
    cast64(H2, F2, tid);

    mm64h<false>(F2, H2, H1, 1.f, 0.f, tid);
#pragma unroll
    for (int it = 0; it < 16; it++) {
        int idx = it * 256 + tid;
        int r = idx >> 6, c = idx & 63;
        F2[r * LDm + c] += ((r == c) ? 1.f : 0.f)
                         + F0[r * LDm + c] * (1.f / 3.f)
                         + F1[r * LDm + c] * (1.f / 5.f);
    }
    __syncthreads();
    cast64(H1, F2, tid);

    mm64h<false>(F2, H0, H1, 2.f, 0.f, tid);   // Lm

    // ---- Phase B ----
    const __half* qk = g_qkv + (size_t)b * Ll * M3 + H2d * 64;
    for (int h = 0; h < H2d; h++) {
        float hs = head_scales[h];
#pragma unroll
        for (int it = 0; it < 8; it++) {
            int idx = it * 256 + tid;
            int r = idx >> 5, e2 = (idx & 31) * 2;
            const __half* p = qk + (size_t)(n * Cc + r) * M3 + h * 64 + e2;
            *(__half2*)(H0 + r * HP + e2) = *(const __half2*)(p);
            *(__half2*)(H1 + r * HP + e2) = *(const __half2*)(p + Dd);
            *(__half2*)(H2 + r * HP + e2) = *(const __half2*)(p + 2 * Dd);
        }
        __syncthreads();

        attn64_mma(H0, H1, H2, H0, F0, F2, hs,
                   (size_t)b * Ll + (size_t)n * 64, 1, (H2d + h) * 64, tid);
        __syncthreads();
    }
}

// =================================================================
// launch
// =================================================================
extern "C" void kernel_launch(void* const* d_in, const int* in_sizes, int n_in,
                              void* d_out, int out_size)
{
    const float* x     = (const float*)d_in[0];
    const float* qkv_w = (const float*)d_in[1];
    const float* qkv_b = (const float*)d_in[2];
    const float* fc_w  = (const float*)d_in[3];
    const float* fc_b  = (const float*)d_in[4];
    const float* hsc   = (const float*)d_in[5];
    float* out = (float*)d_out;

    __half* p_qkv = nullptr;
    __half* p_abuf = nullptr;
    __half* p_obuf = nullptr;
    __half* p_wbuf = nullptr;
    cudaGetSymbolAddress((void**)&p_qkv, g_qkv);
    cudaGetSymbolAddress((void**)&p_abuf, g_abuf);
    cudaGetSymbolAddress((void**)&p_obuf, g_obuf);
    cudaGetSymbolAddress((void**)&p_wbuf, g_wbuf);

    const int smemT = 3 * 64 * HP * 2 + 64 * LDm * 4;                // 45056
    const int smemS = 80896;
    cudaFuncSetAttribute(temporal_attn, cudaFuncAttributeMaxDynamicSharedMemorySize, smemT);
    cudaFuncSetAttribute(spatial_riemann, cudaFuncAttributeMaxDynamicSharedMemorySize, smemS);
    cudaFuncSetAttribute(gemm_mma<true>,  cudaFuncAttributeMaxDynamicSharedMemorySize, GSM);
    cudaFuncSetAttribute(gemm_mma<false>, cudaFuncAttributeMaxDynamicSharedMemorySize, GSM);

    // 1) cast x and qkv_w to fp16
    {
        size_t tot = (size_t)MROWS * Dd;
        conv_cast<<<(unsigned)(tot / 1024), 256>>>(x, p_abuf, tot);
        size_t totw = (size_t)M3 * Dd;
        conv_cast<<<(unsigned)(totw / 1024), 256>>>(qkv_w, p_wbuf, totw);
    }
    // 2) QKV projection (fp16 output)
    {
        dim3 grid(M3 / BNg, MROWS / BMg);   // (6, 512)
        gemm_mma<true><<<grid, 256, GSM>>>(p_abuf, p_wbuf, qkv_b, p_qkv, M3);
    }
    // 3) SPD log bias + spatial heads -> g_obuf  (reordered: gets ncu slot)
    spatial_riemann<<<Bsz * Nn, 256, smemS>>>(hsc);
    // 4) temporal heads -> g_obuf
    temporal_attn<<<Bsz * Cc * H2d, 256, smemT>>>();
    // 5) cast fc_w to fp16
    {
        size_t totw = (size_t)Dd * Dd;
        conv_cast<<<(unsigned)(totw / 1024), 256>>>(fc_w, p_wbuf, totw);
    }
    // 6) output projection (fp32 output) from g_obuf
    {
        dim3 grid(Dd / BNg, MROWS / BMg);   // (2, 512)
        gemm_mma<false><<<grid, 256, GSM>>>(p_obuf, p_wbuf, fc_b, out, Dd);
    }
}

// round 17
// speedup vs baseline: 1.1012x; 1.1012x over previous
#include <cuda_runtime.h>
#include <cuda_fp16.h>
#include <cstdint>
#include <cstddef>
#include <math.h>

#define H2d 4
#define Bsz 16
#define Cc 64
#define Nn 64
#define Dd 512
#define Ll (Nn*Cc)            // 4096
#define M3 (3*Dd)             // 1536
#define LDm 68                // padded smem pitch (floats)
#define HP 72                 // padded smem pitch (halves) -> 144B
#define SCALE_ATT 0.125f
#define SPD_EPSF 1e-5f

#define MROWS (Bsz*Ll)        // 65536
#define KK 512
#define BK 64
#define NCH 8
#define BMg 128
#define BNg 128
#define APITCH 72
#define STG_TILE (128*APITCH)
#define STAGES 3
#define GSM (STAGES*2*STG_TILE*2)   // 110592

#define NSPAT (Bsz*Nn)        // 1024 spatial blocks

// ---------------- scratch ----------------
__device__ __half g_qkv[(size_t)Bsz * Ll * M3];           // fp16 QKV
__device__ __half g_abuf[(size_t)MROWS * KK];             // fp16 x (stays intact)
__device__ __half g_obuf[(size_t)MROWS * KK];             // fp16 attention outputs
__device__ __half g_wbuf[(size_t)M3 * KK];                // fp16 weights

// =================================================================
// PTX helpers
// =================================================================
__device__ __forceinline__ uint32_t smem_u32(const void* p) {
    uint32_t a;
    asm("{ .reg .u64 t; cvta.to.shared.u64 t, %1; cvt.u32.u64 %0, t; }" : "=r"(a) : "l"(p));
    return a;
}
#define CP_ASYNC16(dst, src) \
    asm volatile("cp.async.cg.shared.global [%0], [%1], 16;" :: "r"(dst), "l"(src))
#define CP_COMMIT() asm volatile("cp.async.commit_group;" ::: "memory")
#define CP_WAIT1()  asm volatile("cp.async.wait_group 1;" ::: "memory")

__device__ __forceinline__ void ldsm_x4(uint32_t& r0, uint32_t& r1, uint32_t& r2,
                                        uint32_t& r3, uint32_t addr) {
    asm volatile("ldmatrix.sync.aligned.m8n8.x4.shared.b16 {%0,%1,%2,%3}, [%4];"
                 : "=r"(r0), "=r"(r1), "=r"(r2), "=r"(r3) : "r"(addr));
}
__device__ __forceinline__ void ldsm_x4_t(uint32_t& r0, uint32_t& r1, uint32_t& r2,
                                          uint32_t& r3, uint32_t addr) {
    asm volatile("ldmatrix.sync.aligned.m8n8.x4.trans.shared.b16 {%0,%1,%2,%3}, [%4];"
                 : "=r"(r0), "=r"(r1), "=r"(r2), "=r"(r3) : "r"(addr));
}
__device__ __forceinline__ void mma16816(float c[4], uint32_t a0, uint32_t a1,
                                         uint32_t a2, uint32_t a3,
                                         uint32_t b0, uint32_t b1) {
    asm volatile(
        "mma.sync.aligned.m16n8k16.row.col.f32.f16.f16.f32 "
        "{%0,%1,%2,%3}, {%4,%5,%6,%7}, {%8,%9}, {%0,%1,%2,%3};"
        : "+f"(c[0]), "+f"(c[1]), "+f"(c[2]), "+f"(c[3])
        : "r"(a0), "r"(a1), "r"(a2), "r"(a3), "r"(b0), "r"(b1));
}

// =================================================================
// fp32 -> fp16 cast (global)
// =================================================================
__global__ void conv_cast(const float* __restrict__ src, __half* __restrict__ dst,
                          size_t total)
{
    size_t i = (size_t)blockIdx.x * blockDim.x + threadIdx.x;
    size_t e = i * 4;
    if (e >= total) return;
    float4 v = *(const float4*)(src + e);
    *(__half2*)(dst + e)     = __floats2half2_rn(v.x, v.y);
    *(__half2*)(dst + e + 2) = __floats2half2_rn(v.z, v.w);
}

// =================================================================
// mma.sync fp16 GEMM: 128x128 CTA tile, occ 2 (validated R13-R15)
// =================================================================
template<bool HALF_OUT>
__global__ __launch_bounds__(256, 2) void gemm_mma(
    const __half* __restrict__ A, const __half* __restrict__ W,
    const float* __restrict__ bias, void* __restrict__ Cv, int Nout)
{
    extern __shared__ __half smg[];
    const int tid = threadIdx.x;
    const int wid = tid >> 5, lane = tid & 31;
    const int g = lane >> 2, tig = lane & 3;
    const int warp_m = wid >> 2, warp_n = wid & 3;
    const int bc = blockIdx.x, br = blockIdx.y;

    const __half* gAb = A + (size_t)(br * BMg) * KK;
    const __half* gBb = W + (size_t)(bc * BNg) * KK;

    const uint32_t smb = smem_u32(smg);

    auto load_chunk = [&](int kc, int s) {
        const uint32_t smA = smb + (uint32_t)(s * 2 * STG_TILE) * 2;
        const uint32_t smB = smA + (uint32_t)STG_TILE * 2;
        const __half* gA = gAb + kc * BK;
        const __half* gB = gBb + kc * BK;
#pragma unroll
        for (int i = 0; i < 4; i++) {
            int idx = i * 256 + tid;
            int r = idx >> 3, c16 = idx & 7;
            CP_ASYNC16(smA + r * (APITCH * 2) + c16 * 16, gA + (size_t)r * KK + c16 * 8);
        }
#pragma unroll
        for (int i = 0; i < 4; i++) {
            int idx = i * 256 + tid;
            int r = idx >> 3, c16 = idx & 7;
            CP_ASYNC16(smB + r * (APITCH * 2) + c16 * 16, gB + (size_t)r * KK + c16 * 8);
        }
    };

    float acc[4][4][4];
#pragma unroll
    for (int mt = 0; mt < 4; mt++)
#pragma unroll
        for (int nt = 0; nt < 4; nt++)
#pragma unroll
            for (int q = 0; q < 4; q++) acc[mt][nt][q] = 0.f;

    const int a_row = warp_m * 64 + (lane & 15);
    const int a_kof = (lane >> 4) * 8;
    const int b_col = warp_n * 32 + (lane & 7) + ((lane >> 4) << 3);
    const int b_kof = ((lane >> 3) & 1) * 8;

    load_chunk(0, 0); CP_COMMIT();
    load_chunk(1, 1); CP_COMMIT();

    for (int kc = 0; kc < NCH; kc++) {
        CP_WAIT1();
        __syncthreads();
        if (kc + 2 < NCH) load_chunk(kc + 2, (kc + 2) % STAGES);
        CP_COMMIT();

        const int s = kc % STAGES;
        const uint32_t smA = smb + (uint32_t)(s * 2 * STG_TILE) * 2;
        const uint32_t smB = smA + (uint32_t)STG_TILE * 2;

#pragma unroll
        for (int ks = 0; ks < 4; ks++) {
            const int kb = ks * 16;
            uint32_t af[4][4], bf[2][4];
#pragma unroll
            for (int mt = 0; mt < 4; mt++) {
                uint32_t addr = smA + (uint32_t)(((a_row + mt * 16) * APITCH) + kb + a_kof) * 2;
                ldsm_x4(af[mt][0], af[mt][1], af[mt][2], af[mt][3], addr);
            }
#pragma unroll
            for (int ntp = 0; ntp < 2; ntp++) {
                uint32_t addr = smB + (uint32_t)(((b_col + ntp * 16) * APITCH) + kb + b_kof) * 2;
                ldsm_x4(bf[ntp][0], bf[ntp][1], bf[ntp][2], bf[ntp][3], addr);
            }
#pragma unroll
            for (int mt = 0; mt < 4; mt++)
#pragma unroll
                for (int ntp = 0; ntp < 2; ntp++) {
                    mma16816(acc[mt][2 * ntp],     af[mt][0], af[mt][1], af[mt][2], af[mt][3],
                             bf[ntp][0], bf[ntp][1]);
                    mma16816(acc[mt][2 * ntp + 1], af[mt][0], af[mt][1], af[mt][2], af[mt][3],
                             bf[ntp][2], bf[ntp][3]);
                }
        }
    }

#pragma unroll
    for (int mt = 0; mt < 4; mt++) {
        int row0 = br * BMg + warp_m * 64 + mt * 16 + g;
#pragma unroll
        for (int nt = 0; nt < 4; nt++) {
            int col = bc * BNg + warp_n * 32 + nt * 8 + 2 * tig;
            float b0 = bias[col], b1 = bias[col + 1];
            if (HALF_OUT) {
                __half* C = (__half*)Cv;
                *(__half2*)(C + (size_t)row0 * Nout + col) =
                    __floats2half2_rn(acc[mt][nt][0] + b0, acc[mt][nt][1] + b1);
                *(__half2*)(C + (size_t)(row0 + 8) * Nout + col) =
                    __floats2half2_rn(acc[mt][nt][2] + b0, acc[mt][nt][3] + b1);
            } else {
                float* C = (float*)Cv;
                *(float2*)(C + (size_t)row0 * Nout + col) =
                    make_float2(acc[mt][nt][0] + b0, acc[mt][nt][1] + b1);
                *(float2*)(C + (size_t)(row0 + 8) * Nout + col) =
                    make_float2(acc[mt][nt][2] + b0, acc[mt][nt][3] + b1);
            }
        }
    }
}

// =================================================================
// Scalar 64x64 matmul helpers (fp32; final NS iter only)
// =================================================================
__device__ __forceinline__ void mm64s_acc(float acc[4][4],
                                          const float* __restrict__ Am,
                                          const float* __restrict__ Bm,
                                          int tx, int ty)
{
#pragma unroll 8
    for (int k = 0; k < 64; k++) {
        float4 bv = *(const float4*)(Bm + k * LDm + 4 * tx);
        float a0 = Am[(4 * ty + 0) * LDm + k];
        float a1 = Am[(4 * ty + 1) * LDm + k];
        float a2 = Am[(4 * ty + 2) * LDm + k];
        float a3 = Am[(4 * ty + 3) * LDm + k];
        acc[0][0] += a0 * bv.x; acc[0][1] += a0 * bv.y; acc[0][2] += a0 * bv.z; acc[0][3] += a0 * bv.w;
        acc[1][0] += a1 * bv.x; acc[1][1] += a1 * bv.y; acc[1][2] += a1 * bv.z; acc[1][3] += a1 * bv.w;
        acc[2][0] += a2 * bv.x; acc[2][1] += a2 * bv.y; acc[2][2] += a2 * bv.z; acc[2][3] += a2 * bv.w;
        acc[3][0] += a3 * bv.x; acc[3][1] += a3 * bv.y; acc[3][2] += a3 * bv.z; acc[3][3] += a3 * bv.w;
    }
}
__device__ __forceinline__ void mm64(float* __restrict__ dst,
                                     const float* __restrict__ Am,
                                     const float* __restrict__ Bm,
                                     int tx, int ty, float dscale, float diagadd)
{
    float acc[4][4] = {};
    mm64s_acc(acc, Am, Bm, tx, ty);
#pragma unroll
    for (int i = 0; i < 4; i++)
#pragma unroll
        for (int j = 0; j < 4; j++) {
            int r = 4 * ty + i, c = 4 * tx + j;
            dst[r * LDm + c] = acc[i][j] * dscale + ((r == c) ? diagadd : 0.f);
        }
    __syncthreads();
}

// =================================================================
// mma 64x64 matmul on smem fp16 operands, fp32 smem output.
// =================================================================
__device__ __forceinline__ void mm64h_store(float* dst, const float acc[4][4],
                                            int m0, int n0, int g, int tig,
                                            float dscale, float diagadd)
{
#pragma unroll
    for (int nt = 0; nt < 4; nt++) {
        int r = m0 + g, c = n0 + nt * 8 + 2 * tig;
        dst[r * LDm + c]           = acc[nt][0] * dscale + ((r == c)         ? diagadd : 0.f);
        dst[r * LDm + c + 1]       = acc[nt][1] * dscale + ((r == c + 1)     ? diagadd : 0.f);
        dst[(r + 8) * LDm + c]     = acc[nt][2] * dscale + ((r + 8 == c)     ? diagadd : 0.f);
        dst[(r + 8) * LDm + c + 1] = acc[nt][3] * dscale + ((r + 8 == c + 1) ? diagadd : 0.f);
    }
}

template<bool TRANS>
__device__ __forceinline__ void mm64h(float* dst, const __half* Ah, const __half* Bh,
                                      float dscale, float diagadd, int tid)
{
    const int wid = tid >> 5, lane = tid & 31;
    const int g = lane >> 2, tig = lane & 3;
    const int m0 = (wid >> 1) * 16, n0 = (wid & 1) * 32;
    const uint32_t ab = smem_u32(Ah), bb = smem_u32(Bh);
    const int a_off = (m0 + (lane & 15)) * HP + (lane >> 4) * 8;
    const int b_off = (n0 + (lane & 7) + ((lane >> 4) << 3)) * HP + ((lane >> 3) & 1) * 8;
    const int v_off = (lane & 15) * HP + n0 + ((lane >> 4) << 3);

    float acc[4][4];
#pragma unroll
    for (int i = 0; i < 4; i++)
#pragma unroll
        for (int j = 0; j < 4; j++) acc[i][j] = 0.f;

#pragma unroll
    for (int ks = 0; ks < 4; ks++) {
        uint32_t a[4], b0[4], b1[4];
        ldsm_x4(a[0], a[1], a[2], a[3], ab + (uint32_t)(a_off + ks * 16) * 2);
        if (TRANS) {
            ldsm_x4_t(b0[0], b0[1], b0[2], b0[3], bb + (uint32_t)(v_off + ks * 16 * HP) * 2);
            ldsm_x4_t(b1[0], b1[1], b1[2], b1[3], bb + (uint32_t)(v_off + ks * 16 * HP + 16) * 2);
        } else {
            ldsm_x4(b0[0], b0[1], b0[2], b0[3], bb + (uint32_t)(b_off + ks * 16) * 2);
            ldsm_x4(b1[0], b1[1], b1[2], b1[3], bb + (uint32_t)(b_off + 16 * HP + ks * 16) * 2);
        }
        mma16816(acc[0], a[0], a[1], a[2], a[3], b0[0], b0[1]);
        mma16816(acc[1], a[0], a[1], a[2], a[3], b0[2], b0[3]);
        mma16816(acc[2], a[0], a[1], a[2], a[3], b1[0], b1[1]);
        mma16816(acc[3], a[0], a[1], a[2], a[3], b1[2], b1[3]);
    }
    mm64h_store(dst, acc, m0, n0, g, tig, dscale, diagadd);
    __syncthreads();
}

// cast 64x64 fp32 (pitch LDm) -> fp16 (pitch HP); trailing sync
__device__ __forceinline__ void cast64(__half* dst, const float* src, int tid)
{
#pragma unroll
    for (int it = 0; it < 4; it++) {
        int idx = it * 256 + tid;
        int r = idx >> 4, c4 = (idx & 15) * 4;
        float4 v = *(const float4*)(src + r * LDm + c4);
        *(__half2*)(dst + r * HP + c4)     = __floats2half2_rn(v.x, v.y);
        *(__half2*)(dst + r * HP + c4 + 2) = __floats2half2_rn(v.z, v.w);
    }
    __syncthreads();
}

// =================================================================
// attn64_mma (validated R14/R15)
// =================================================================
__device__ __forceinline__ void attn64_mma(
    const __half* Qh, const __half* Kh, const __half* Vh, __half* Ph,
    float* Sf, const float* bias, float hs,
    size_t rowbase, int rstride, int colbase, int tid)
{
    const int wid = tid >> 5, lane = tid & 31;
    const int g = lane >> 2, tig = lane & 3;
    const int m0 = (wid >> 1) * 16, n0 = (wid & 1) * 32;

    const uint32_t qb = smem_u32(Qh);
    const uint32_t kb = smem_u32(Kh);
    const uint32_t vb = smem_u32(Vh);
    const uint32_t pb = smem_u32(Ph);

    const int a_off = (m0 + (lane & 15)) * HP + (lane >> 4) * 8;
    const int b_off = (n0 + (lane & 7) + ((lane >> 4) << 3)) * HP + ((lane >> 3) & 1) * 8;
    const int v_off = (lane & 15) * HP + n0 + ((lane >> 4) << 3);

    float acc[4][4];
#pragma unroll
    for (int i = 0; i < 4; i++)
#pragma unroll
        for (int j = 0; j < 4; j++) acc[i][j] = 0.f;

#pragma unroll
    for (int ks = 0; ks < 4; ks++) {
        uint32_t a[4], b0[4], b1[4];
        ldsm_x4(a[0], a[1], a[2], a[3], qb + (uint32_t)(a_off + ks * 16) * 2);
        ldsm_x4(b0[0], b0[1], b0[2], b0[3], kb + (uint32_t)(b_off + ks * 16) * 2);
        ldsm_x4(b1[0], b1[1], b1[2], b1[3], kb + (uint32_t)(b_off + 16 * HP + ks * 16) * 2);
        mma16816(acc[0], a[0], a[1], a[2], a[3], b0[0], b0[1]);
        mma16816(acc[1], a[0], a[1], a[2], a[3], b0[2], b0[3]);
        mma16816(acc[2], a[0], a[1], a[2], a[3], b1[0], b1[1]);
        mma16816(acc[3], a[0], a[1], a[2], a[3], b1[2], b1[3]);
    }
#pragma unroll
    for (int nt = 0; nt < 4; nt++) {
        int r = m0 + g, c = n0 + nt * 8 + 2 * tig;
        float s0 = acc[nt][0] * SCALE_ATT, s1 = acc[nt][1] * SCALE_ATT;
        float s2 = acc[nt][2] * SCALE_ATT, s3 = acc[nt][3] * SCALE_ATT;
        if (bias) {
            s0 += hs * bias[r * LDm + c];       s1 += hs * bias[r * LDm + c + 1];
            s2 += hs * bias[(r + 8) * LDm + c]; s3 += hs * bias[(r + 8) * LDm + c + 1];
        }
        Sf[r * LDm + c] = s0;       Sf[r * LDm + c + 1] = s1;
        Sf[(r + 8) * LDm + c] = s2; Sf[(r + 8) * LDm + c + 1] = s3;
    }
    __syncthreads();

    {
        int row = tid >> 2, seg = tid & 3;
        const float* src = Sf + row * LDm + seg * 16;
        float vv[16];
        float4 t0 = *(const float4*)(src);
        float4 t1 = *(const float4*)(src + 4);
        float4 t2 = *(const float4*)(src + 8);
        float4 t3 = *(const float4*)(src + 12);
        vv[0] = t0.x; vv[1] = t0.y; vv[2] = t0.z; vv[3] = t0.w;
        vv[4] = t1.x; vv[5] = t1.y; vv[6] = t1.z; vv[7] = t1.w;
        vv[8] = t2.x; vv[9] = t2.y; vv[10] = t2.z; vv[11] = t2.w;
        vv[12] = t3.x; vv[13] = t3.y; vv[14] = t3.z; vv[15] = t3.w;
        float m = vv[0];
#pragma unroll
        for (int j = 1; j < 16; j++) m = fmaxf(m, vv[j]);
        m = fmaxf(m, __shfl_xor_sync(0xffffffffu, m, 1, 4));
        m = fmaxf(m, __shfl_xor_sync(0xffffffffu, m, 2, 4));
        float s = 0.f;
#pragma unroll
        for (int j = 0; j < 16; j++) { vv[j] = __expf(vv[j] - m); s += vv[j]; }
        s += __shfl_xor_sync(0xffffffffu, s, 1, 4);
        s += __shfl_xor_sync(0xffffffffu, s, 2, 4);
        float inv = 1.f / s;
        __half* d = Ph + row * HP + seg * 16;
#pragma unroll
        for (int j = 0; j < 8; j++)
            *(__half2*)(d + 2 * j) = __floats2half2_rn(vv[2 * j] * inv, vv[2 * j + 1] * inv);
    }
    __syncthreads();

    float o[4][4];
#pragma unroll
    for (int i = 0; i < 4; i++)
#pragma unroll
        for (int j = 0; j < 4; j++) o[i][j] = 0.f;

#pragma unroll
    for (int ks = 0; ks < 4; ks++) {
        uint32_t a[4], b0[4], b1[4];
        ldsm_x4(a[0], a[1], a[2], a[3], pb + (uint32_t)(a_off + ks * 16) * 2);
        ldsm_x4_t(b0[0], b0[1], b0[2], b0[3], vb + (uint32_t)(v_off + ks * 16 * HP) * 2);
        ldsm_x4_t(b1[0], b1[1], b1[2], b1[3], vb + (uint32_t)(v_off + ks * 16 * HP + 16) * 2);
        mma16816(o[0], a[0], a[1], a[2], a[3], b0[0], b0[1]);
        mma16816(o[1], a[0], a[1], a[2], a[3], b0[2], b0[3]);
        mma16816(o[2], a[0], a[1], a[2], a[3], b1[0], b1[1]);
        mma16816(o[3], a[0], a[1], a[2], a[3], b1[2], b1[3]);
    }
#pragma unroll
    for (int nt = 0; nt < 4; nt++) {
        int r = m0 + g, c = colbase + n0 + nt * 8 + 2 * tig;
        __half* d0 = g_obuf + (rowbase + (size_t)r * rstride) * KK + c;
        __half* d1 = g_obuf + (rowbase + (size_t)(r + 8) * rstride) * KK + c;
        *(__half2*)d0 = __floats2half2_rn(o[nt][0], o[nt][1]);
        *(__half2*)d1 = __floats2half2_rn(o[nt][2], o[nt][3]);
    }
}

// =================================================================
// Temporal body (validated R14)
// =================================================================
__device__ __forceinline__ void temporal_body(int bid, int tid, char* smT)
{
    __half* Qh = (__half*)smT;
    __half* Kh = Qh + 64 * HP;
    __half* Vh = Kh + 64 * HP;
    float*  Sf = (float*)(smT + 3 * 64 * HP * 2);
    const int h = bid & 3;
    const int c = (bid >> 2) & 63;
    const int b = bid >> 8;

    const __half* qk = g_qkv + (size_t)b * Ll * M3 + h * 64;
#pragma unroll
    for (int it = 0; it < 8; it++) {
        int idx = it * 256 + tid;
        int nn = idx >> 5, e2 = (idx & 31) * 2;
        const __half* p = qk + (size_t)(nn * Cc + c) * M3 + e2;
        *(__half2*)(Qh + nn * HP + e2) = *(const __half2*)(p);
        *(__half2*)(Kh + nn * HP + e2) = *(const __half2*)(p + Dd);
        *(__half2*)(Vh + nn * HP + e2) = *(const __half2*)(p + 2 * Dd);
    }
    __syncthreads();

    attn64_mma(Qh, Kh, Vh, Qh, Sf, nullptr, 0.f,
               (size_t)b * Ll + c, 64, h * 64, tid);
}

// =================================================================
// Spatial body (validated R15)
// =================================================================
__device__ __forceinline__ void spatial_body(int bid, int tid, char* smS,
                                             const float* head_scales,
                                             float* s_alpha)
{
    float* F0 = (float*)smS;
    float* F1 = (float*)(smS + 17408);
    float* F2 = (float*)(smS + 34816);
    __half* H0 = (__half*)(smS + 52224);
    __half* H1 = (__half*)(smS + 61440);
    __half* H2 = (__half*)(smS + 70656);
    float* red = (float*)(smS + 79872);

    const int tx = tid & 15, ty = tid >> 4;
    const int lane = tid & 31, wid = tid >> 5;
    const int g = lane >> 2, tig = lane & 3;
    const int m0 = (wid >> 1) * 16, n0 = (wid & 1) * 32;
    const int n = bid & 63, b = bid >> 6;

    // ---- A = X X^T / D + (1+eps) I ----
    {
        const size_t xrow0 = (size_t)b * Ll + (size_t)n * Cc;
        float sacc[4][4];
#pragma unroll
        for (int i = 0; i < 4; i++)
#pragma unroll
            for (int j = 0; j < 4; j++) sacc[i][j] = 0.f;

        const uint32_t xb = smem_u32(H0);
        const int a_off = (m0 + (lane & 15)) * HP + (lane >> 4) * 8;
        const int b_off = (n0 + (lane & 7) + ((lane >> 4) << 3)) * HP + ((lane >> 3) & 1) * 8;

        for (int kc = 0; kc < 8; kc++) {
#pragma unroll
            for (int it = 0; it < 8; it++) {
                int idx = it * 256 + tid;
                int r = idx >> 5, e2 = (idx & 31) * 2;
                *(__half2*)(H0 + r * HP + e2) =
                    *(const __half2*)(g_abuf + (xrow0 + r) * KK + kc * 64 + e2);
            }
            __syncthreads();
#pragma unroll
            for (int ks = 0; ks < 4; ks++) {
                uint32_t a[4], b0[4], b1[4];
                ldsm_x4(a[0], a[1], a[2], a[3], xb + (uint32_t)(a_off + ks * 16) * 2);
                ldsm_x4(b0[0], b0[1], b0[2], b0[3], xb + (uint32_t)(b_off + ks * 16) * 2);
                ldsm_x4(b1[0], b1[1], b1[2], b1[3], xb + (uint32_t)(b_off + 16 * HP + ks * 16) * 2);
                mma16816(sacc[0], a[0], a[1], a[2], a[3], b0[0], b0[1]);
                mma16816(sacc[1], a[0], a[1], a[2], a[3], b0[2], b0[3]);
                mma16816(sacc[2], a[0], a[1], a[2], a[3], b1[0], b1[1]);
                mma16816(sacc[3], a[0], a[1], a[2], a[3], b1[2], b1[3]);
            }
            __syncthreads();
        }
        mm64h_store(F0, sacc, m0, n0, g, tig, 1.f / (float)Dd, 1.f + SPD_EPSF);
        __syncthreads();
    }

    // ---- Gershgorin -> alpha ----
    {
        int r = tid >> 2, seg = tid & 3;
        float s = 0.f;
#pragma unroll
        for (int j = 0; j < 16; j++) s += fabsf(F0[r * LDm + seg * 16 + j]);
        red[tid] = s;
    }
    __syncthreads();
    if (tid == 0) {
        float rmax = 0.f;
        for (int r = 0; r < 64; r++)
            rmax = fmaxf(rmax, red[4 * r] + red[4 * r + 1] + red[4 * r + 2] + red[4 * r + 3]);
        *s_alpha = 2.f / (1.f + rmax);
    }
    __syncthreads();
    const float alpha = *s_alpha;

    cast64(H1, F0, tid);
#pragma unroll
    for (int it = 0; it < 16; it++) {
        int idx = it * 256 + tid;
        int r = idx >> 6, c = idx & 63;
        H0[r * HP + c] = __float2half((r == c) ? alpha : 0.f);
    }
    __syncthreads();

    // ---- NS iterations 1-3 in fp16 mma ----
    for (int it = 0; it < 3; it++) {
        mm64h<false>(F1, H1, H0, 1.f, 0.f, tid);
        cast64(H2, F1, tid);
        mm64h<true>(F1, H0, H2, 1.f, 0.f, tid);
#pragma unroll
        for (int i2 = 0; i2 < 16; i2++) {
            int idx = i2 * 256 + tid;
            int r = idx >> 6, c = idx & 63;
            float y = __half2float(H0[r * HP + c]);
            H0[r * HP + c] = __float2half(2.f * y - F1[r * LDm + c]);
        }
        __syncthreads();
    }

    // ---- final NS iteration fp32 ----
#pragma unroll
    for (int it = 0; it < 16; it++) {
        int idx = it * 256 + tid;
        int r = idx >> 6, c = idx & 63;
        F1[r * LDm + c] = __half2float(H0[r * HP + c]);
    }
    __syncthreads();
    {
        const int txl = tid & 15, tyl = tid >> 4;
        mm64(F2, F0, F1, txl, tyl, 1.f, 0.f);
        mm64(F0, F1, F2, txl, tyl, 1.f, 0.f);
    }
#pragma unroll
    for (int it = 0; it < 16; it++) {
        int idx = it * 256 + tid;
        int r = idx >> 6, c = idx & 63;
        float y = 2.f * F1[r * LDm + c] - F0[r * LDm + c];
        H0[r * HP + c] = __float2half(((r == c) ? 1.f : 0.f) - 2.f * y);
    }
    __syncthreads();

    // ---- polynomial chain ----
    mm64h<false>(F0, H0, H0, 1.f, 0.f, tid);   // W
    cast64(H1, F0, tid);
    mm64h<false>(F1, H1, H1, 1.f, 0.f, tid);   // W2
    cast64(H2, F1, tid);
    mm64h<false>(F2, H2, H1, 1.f, 0.f, tid);   // W3
    cast64(H1, F2, tid);

#pragma unroll
    for (int it = 0; it < 16; it++) {
        int idx = it * 256 + tid;
        int r = idx >> 6, c = idx & 63;
        F2[r * LDm + c] = ((r == c) ? (1.f / 7.f) : 0.f)
                        + F0[r * LDm + c] * (1.f / 9.f)
                        + F1[r * LDm + c] * (1.f / 11.f);
    }
    __syncthreads();
    cast64(H2, F2, tid);

    mm64h<false>(F2, H2, H1, 1.f, 0.f, tid);
#pragma unroll
    for (int it = 0; it < 16; it++) {
        int idx = it * 256 + tid;
        int r = idx >> 6, c = idx & 63;
        F2[r * LDm + c] += ((r == c) ? 1.f : 0.f)
                         + F0[r * LDm + c] * (1.f / 3.f)
                         + F1[r * LDm + c] * (1.f / 5.f);
    }
    __syncthreads();
    cast64(H1, F2, tid);

    mm64h<false>(F2, H0, H1, 2.f, 0.f, tid);   // Lm

    // ---- Phase B ----
    const __half* qk = g_qkv + (size_t)b * Ll * M3 + H2d * 64;
    for (int h = 0; h < H2d; h++) {
        float hs = head_scales[h];
#pragma unroll
        for (int it = 0; it < 8; it++) {
            int idx = it * 256 + tid;
            int r = idx >> 5, e2 = (idx & 31) * 2;
            const __half* p = qk + (size_t)(n * Cc + r) * M3 + h * 64 + e2;
            *(__half2*)(H0 + r * HP + e2) = *(const __half2*)(p);
            *(__half2*)(H1 + r * HP + e2) = *(const __half2*)(p + Dd);
            *(__half2*)(H2 + r * HP + e2) = *(const __half2*)(p + 2 * Dd);
        }
        __syncthreads();

        attn64_mma(H0, H1, H2, H0, F0, F2, hs,
                   (size_t)b * Ll + (size_t)n * 64, 1, (H2d + h) * 64, tid);
        __syncthreads();
    }
}

// =================================================================
// Fused attention kernel: blocks [0, NSPAT) = spatial, rest = temporal.
// Spatial blocks first (longer) for better wave scheduling; temporal
// blocks fill issue slots spatial's sync latency leaves idle.
// =================================================================
__global__ __launch_bounds__(256, 2) void attn_fused(const float* __restrict__ head_scales)
{
    extern __shared__ char sm[];
    __shared__ float s_alpha;
    const int tid = threadIdx.x;
    if (blockIdx.x < NSPAT)
        spatial_body(blockIdx.x, tid, sm, head_scales, &s_alpha);
    else
        temporal_body(blockIdx.x - NSPAT, tid, sm);
}

// =================================================================
// launch
// =================================================================
extern "C" void kernel_launch(void* const* d_in, const int* in_sizes, int n_in,
                              void* d_out, int out_size)
{
    const float* x     = (const float*)d_in[0];
    const float* qkv_w = (const float*)d_in[1];
    const float* qkv_b = (const float*)d_in[2];
    const float* fc_w  = (const float*)d_in[3];
    const float* fc_b  = (const float*)d_in[4];
    const float* hsc   = (const float*)d_in[5];
    float* out = (float*)d_out;

    __half* p_qkv = nullptr;
    __half* p_abuf = nullptr;
    __half* p_obuf = nullptr;
    __half* p_wbuf = nullptr;
    cudaGetSymbolAddress((void**)&p_qkv, g_qkv);
    cudaGetSymbolAddress((void**)&p_abuf, g_abuf);
    cudaGetSymbolAddress((void**)&p_obuf, g_obuf);
    cudaGetSymbolAddress((void**)&p_wbuf, g_wbuf);

    const int smemF = 80896;   // max(spatial 80896, temporal 45056)
    cudaFuncSetAttribute(attn_fused, cudaFuncAttributeMaxDynamicSharedMemorySize, smemF);
    cudaFuncSetAttribute(gemm_mma<true>,  cudaFuncAttributeMaxDynamicSharedMemorySize, GSM);
    cudaFuncSetAttribute(gemm_mma<false>, cudaFuncAttributeMaxDynamicSharedMemorySize, GSM);

    // 1) cast x and qkv_w to fp16
    {
        size_t tot = (size_t)MROWS * Dd;
        conv_cast<<<(unsigned)(tot / 1024), 256>>>(x, p_abuf, tot);
        size_t totw = (size_t)M3 * Dd;
        conv_cast<<<(unsigned)(totw / 1024), 256>>>(qkv_w, p_wbuf, totw);
    }
    // 2) QKV projection (fp16 output)
    {
        dim3 grid(M3 / BNg, MROWS / BMg);   // (12, 512)
        gemm_mma<true><<<grid, 256, GSM>>>(p_abuf, p_wbuf, qkv_b, p_qkv, M3);
    }
    // 3) fused spatial + temporal attention -> g_obuf
    attn_fused<<<NSPAT + Bsz * Cc * H2d, 256, smemF>>>(hsc);
    // 4) cast fc_w to fp16
    {
        size_t totw = (size_t)Dd * Dd;
        conv_cast<<<(unsigned)(totw / 1024), 256>>>(fc_w, p_wbuf, totw);
    }
    // 5) output projection (fp32 output) from g_obuf
    {
        dim3 grid(Dd / BNg, MROWS / BMg);   // (4, 512)
        gemm_mma<false><<<grid, 256, GSM>>>(p_obuf, p_wbuf, fc_b, out, Dd);
    }
}